// round 1
// baseline (speedup 1.0000x reference)
#include <cuda_runtime.h>

#define BB 8
#define CC 64
#define HH 128
#define WW 128
#define HWSZ (HH*WW)
#define KOFF 18

// scratch (no allocations allowed)
__device__ float g_offset[BB*KOFF*HWSZ];   // post-PReLU offsets [B,18,H,W]
__device__ float g_feat  [BB*CC*HWSZ];     // deformable conv output [B,64,H,W]

typedef unsigned long long u64;

__device__ __forceinline__ u64 pk2(float lo, float hi){
    u64 r; asm("mov.b64 %0, {%1,%2};" : "=l"(r) : "f"(lo), "f"(hi)); return r;
}
__device__ __forceinline__ float2 uf2(u64 v){
    float2 f; asm("mov.b64 {%0,%1}, %2;" : "=f"(f.x), "=f"(f.y) : "l"(v)); return f;
}
__device__ __forceinline__ u64 fma2(u64 a, u64 b, u64 c){
    u64 d; asm("fma.rn.f32x2 %0, %1, %2, %3;" : "=l"(d) : "l"(a), "l"(b), "l"(c)); return d;
}

// ---------------------------------------------------------------------------
// K1: offset conv (Cout=18, 3x3, pad 1) + bias + PReLU -> g_offset
// block 256 = 32 w-quads x 2 outch-halves x 4 rows; grid 256 = 8 b x 32 h-quads
// ---------------------------------------------------------------------------
__global__ __launch_bounds__(256, 2) void k_offset(
    const float* __restrict__ x, const float* __restrict__ offw,
    const float* __restrict__ offb, const float* __restrict__ pa_)
{
    extern __shared__ u64 s_w2[];   // 18*64*9 dup'd weights
    int t = threadIdx.x;
    for (int i = t; i < KOFF*CC*9; i += 256) { float v = offw[i]; s_w2[i] = pk2(v, v); }
    __syncthreads();

    int b  = blockIdx.x >> 5;
    int h0 = (blockIdx.x & 31) << 2;
    int wq = t & 31, oh = (t >> 5) & 1, r = t >> 6;
    int h = h0 + r, w0 = wq << 2;

    u64 acc[9][2];
    #pragma unroll
    for (int o = 0; o < 9; o++) {
        float bo = offb[oh*9 + o];
        acc[o][0] = pk2(bo, bo); acc[o][1] = acc[o][0];
    }

    const float* xb = x + b*CC*HWSZ;
    for (int c = 0; c < CC; c++) {
        const float* xc = xb + c*HWSZ;
        #pragma unroll
        for (int ky = 0; ky < 3; ky++) {
            int iy = h + ky - 1;
            bool ok = (iy >= 0) && (iy < HH);
            const float* xr = xc + iy*WW;
            float4 Bv = make_float4(0.f, 0.f, 0.f, 0.f);
            float A = 0.f, Cv = 0.f;
            if (ok) {
                Bv = *(const float4*)(xr + w0);
                if (wq > 0)  A  = xr[w0 - 1];
                if (wq < 31) Cv = xr[w0 + 4];
            }
            u64 P[5];
            P[0] = pk2(A,    Bv.x); P[1] = pk2(Bv.x, Bv.y); P[2] = pk2(Bv.y, Bv.z);
            P[3] = pk2(Bv.z, Bv.w); P[4] = pk2(Bv.w, Cv);
            const u64* wrow = s_w2 + ((oh*9)*CC + c)*9 + ky*3;
            #pragma unroll
            for (int kx = 0; kx < 3; kx++) {
                #pragma unroll
                for (int o = 0; o < 9; o++) {
                    u64 wv = wrow[o*CC*9 + kx];
                    acc[o][0] = fma2(wv, P[kx],     acc[o][0]);
                    acc[o][1] = fma2(wv, P[kx + 2], acc[o][1]);
                }
            }
        }
    }

    float pa = pa_[0];
    #pragma unroll
    for (int o = 0; o < 9; o++) {
        float2 u0 = uf2(acc[o][0]), u1 = uf2(acc[o][1]);
        float v0 = u0.x, v1 = u0.y, v2 = u1.x, v3 = u1.y;
        v0 = v0 >= 0.f ? v0 : pa*v0;
        v1 = v1 >= 0.f ? v1 : pa*v1;
        v2 = v2 >= 0.f ? v2 : pa*v2;
        v3 = v3 >= 0.f ? v3 : pa*v3;
        float4 ov = make_float4(v0, v1, v2, v3);
        *(float4*)&g_offset[((b*KOFF + oh*9 + o)*HH + h)*WW + w0] = ov;
    }
}

// ---------------------------------------------------------------------------
// K2: deformable grouped conv (groups=8, Cin/g=8, 3x3, pad 1) -> g_feat
// block 256 = 64 w-pairs x 4 groups; grid 2048 = (b,h) x 2 group-halves
// ---------------------------------------------------------------------------
__global__ __launch_bounds__(256, 2) void k_deform(
    const float* __restrict__ x, const float* __restrict__ dw,
    const float* __restrict__ db)
{
    extern __shared__ float smem[];
    float* soff = smem;                          // 18*128 floats
    u64*   sw2  = (u64*)(smem + KOFF*WW);        // 64*8*9 dup'd weights

    int t = threadIdx.x;
    int bh = blockIdx.x >> 1;
    int b = bh >> 7, h = bh & 127;
    int ghalf = blockIdx.x & 1;

    for (int i = t; i < KOFF*WW; i += 256)
        soff[i] = g_offset[(b*KOFF + (i >> 7))*HWSZ + h*WW + (i & 127)];
    for (int i = t; i < CC*8*9; i += 256) { float v = dw[i]; sw2[i] = pk2(v, v); }
    __syncthreads();

    int wp = t & 63, gl = t >> 6;
    int g = ghalf*4 + gl;
    int w0 = wp*2;

    u64 acc[8];
    #pragma unroll
    for (int o = 0; o < 8; o++) { float bo = db[g*8 + o]; acc[o] = pk2(bo, bo); }

    const float* xg = x + (b*CC + g*8)*HWSZ;

    #pragma unroll
    for (int k = 0; k < 9; k++) {
        int ky = k / 3, kx = k % 3;
        int i00[2], i01[2], i10[2], i11[2];
        float c00[2], c01[2], c10[2], c11[2];
        #pragma unroll
        for (int p = 0; p < 2; p++) {
            int w = w0 + p;
            float dy = soff[(2*k)*WW + w];
            float dx = soff[(2*k + 1)*WW + w];
            float ys = (float)(h - 1 + ky) + dy;
            float xs = (float)(w - 1 + kx) + dx;
            float yf = floorf(ys), xf = floorf(xs);
            float ay = ys - yf, ax = xs - xf;
            int iy0 = (int)yf, ix0 = (int)xf;
            float my0 = (iy0 >= 0  && iy0 < HH)      ? 1.f : 0.f;
            float my1 = (iy0 >= -1 && iy0 + 1 < HH)  ? 1.f : 0.f;
            float mx0 = (ix0 >= 0  && ix0 < WW)      ? 1.f : 0.f;
            float mx1 = (ix0 >= -1 && ix0 + 1 < WW)  ? 1.f : 0.f;
            int cy0 = min(max(iy0, 0), HH - 1), cy1 = min(max(iy0 + 1, 0), HH - 1);
            int cx0 = min(max(ix0, 0), WW - 1), cx1 = min(max(ix0 + 1, 0), WW - 1);
            c00[p] = (1.f - ay)*(1.f - ax)*my0*mx0;
            c01[p] = (1.f - ay)*ax*my0*mx1;
            c10[p] = ay*(1.f - ax)*my1*mx0;
            c11[p] = ay*ax*my1*mx1;
            i00[p] = cy0*WW + cx0; i01[p] = cy0*WW + cx1;
            i10[p] = cy1*WW + cx0; i11[p] = cy1*WW + cx1;
        }
        const u64* wk = sw2 + (g*8)*8*9 + k;
        #pragma unroll
        for (int ci = 0; ci < 8; ci++) {
            const float* xc = xg + ci*HWSZ;
            float v0 = c00[0]*xc[i00[0]] + c01[0]*xc[i01[0]]
                     + c10[0]*xc[i10[0]] + c11[0]*xc[i11[0]];
            float v1 = c00[1]*xc[i00[1]] + c01[1]*xc[i01[1]]
                     + c10[1]*xc[i10[1]] + c11[1]*xc[i11[1]];
            u64 val = pk2(v0, v1);
            #pragma unroll
            for (int o = 0; o < 8; o++)
                acc[o] = fma2(wk[(o*8 + ci)*9], val, acc[o]);
        }
    }

    #pragma unroll
    for (int o = 0; o < 8; o++) {
        float2 f = uf2(acc[o]);
        *(float2*)&g_feat[((b*CC + g*8 + o)*HH + h)*WW + w0] = f;
    }
}

// ---------------------------------------------------------------------------
// K3: 64ch conv (3x3, pad 1, no bias) fused with softmax over W and
//     out = atten * feat + x.  block 256 = 32 w-quads x 8 outch-groups.
//     grid 1024 = (b,h). Full-row x tile in smem, weights chunked by 16 cin.
// ---------------------------------------------------------------------------
__global__ __launch_bounds__(256, 1) void k_conv_softmax(
    const float* __restrict__ x, const float* __restrict__ cw,
    float* __restrict__ out)
{
    extern __shared__ float smem3[];
    float* smx = smem3;                          // 64*3*132 floats
    u64*   sw2 = (u64*)(smem3 + 64*3*132);       // 64*16*9 dup'd weight chunk

    int t = threadIdx.x;
    int b = blockIdx.x >> 7, h = blockIdx.x & 127;

    // x tile: rows h-1..h+1, padded width 130 (stride 132)
    for (int i = t; i < CC*3*130; i += 256) {
        int c = i / 390; int rem = i - c*390;
        int r = rem / 130; int pc = rem - r*130;
        int iy = h + r - 1, iw = pc - 1;
        float v = 0.f;
        if (iy >= 0 && iy < HH && iw >= 0 && iw < WW)
            v = x[(b*CC + c)*HWSZ + iy*WW + iw];
        smx[(c*3 + r)*132 + pc] = v;
    }

    int wq = t & 31, og = t >> 5;
    int w0 = wq << 2;

    u64 acc[8][2];
    #pragma unroll
    for (int o = 0; o < 8; o++) { acc[o][0] = 0ULL; acc[o][1] = 0ULL; }

    for (int cch = 0; cch < 4; cch++) {
        __syncthreads();
        for (int i = t; i < CC*16*9; i += 256) {
            int o = i / 144; int rem = i - o*144;     // cl*9 + tap
            float v = cw[(o*CC + cch*16)*9 + rem];
            sw2[i] = pk2(v, v);
        }
        __syncthreads();
        #pragma unroll 1
        for (int cl = 0; cl < 16; cl++) {
            int cg = cch*16 + cl;
            #pragma unroll
            for (int ky = 0; ky < 3; ky++) {
                const float* xr = smx + (cg*3 + ky)*132;
                float4 Bv = *(const float4*)(xr + w0);
                float2 Cv = *(const float2*)(xr + w0 + 4);
                u64 P[5];
                P[0] = pk2(Bv.x, Bv.y); P[1] = pk2(Bv.y, Bv.z); P[2] = pk2(Bv.z, Bv.w);
                P[3] = pk2(Bv.w, Cv.x); P[4] = pk2(Cv.x, Cv.y);
                const u64* wr = sw2 + (og*8)*144 + cl*9 + ky*3;
                #pragma unroll
                for (int kx = 0; kx < 3; kx++) {
                    #pragma unroll
                    for (int o = 0; o < 8; o++) {
                        u64 wv = wr[o*144 + kx];
                        acc[o][0] = fma2(wv, P[kx],     acc[o][0]);
                        acc[o][1] = fma2(wv, P[kx + 2], acc[o][1]);
                    }
                }
            }
        }
    }

    // softmax over W (warp owns the full 128-wide row per channel) + combine
    #pragma unroll
    for (int o = 0; o < 8; o++) {
        int oc = og*8 + o;
        float2 u0 = uf2(acc[o][0]), u1 = uf2(acc[o][1]);
        float v0 = u0.x, v1 = u0.y, v2 = u1.x, v3 = u1.y;
        float m = fmaxf(fmaxf(v0, v1), fmaxf(v2, v3));
        #pragma unroll
        for (int s = 16; s > 0; s >>= 1)
            m = fmaxf(m, __shfl_xor_sync(0xffffffffu, m, s));
        float e0 = __expf(v0 - m), e1 = __expf(v1 - m);
        float e2 = __expf(v2 - m), e3 = __expf(v3 - m);
        float sm = e0 + e1 + e2 + e3;
        #pragma unroll
        for (int s = 16; s > 0; s >>= 1)
            sm += __shfl_xor_sync(0xffffffffu, sm, s);
        float inv = 1.0f / sm;
        int base = ((b*CC + oc)*HH + h)*WW + w0;
        float4 ft = *(const float4*)&g_feat[base];
        float4 rx = *(const float4*)&x[base];
        float4 ov = make_float4(fmaf(e0*inv, ft.x, rx.x),
                                fmaf(e1*inv, ft.y, rx.y),
                                fmaf(e2*inv, ft.z, rx.z),
                                fmaf(e3*inv, ft.w, rx.w));
        *(float4*)&out[base] = ov;
    }
}

extern "C" void kernel_launch(void* const* d_in, const int* in_sizes, int n_in,
                              void* d_out, int out_size)
{
    const float* x    = (const float*)d_in[0];
    const float* offw = (const float*)d_in[1];
    const float* offb = (const float*)d_in[2];
    const float* pa   = (const float*)d_in[3];
    const float* dw   = (const float*)d_in[4];
    const float* db   = (const float*)d_in[5];
    const float* cw   = (const float*)d_in[6];
    float* out = (float*)d_out;

    const int smem1 = KOFF*CC*9*8;                       // 82944
    const int smem2 = KOFF*WW*4 + CC*8*9*8;              // 46080
    const int smem3 = 64*3*132*4 + 64*16*9*8;            // 175104

    cudaFuncSetAttribute(k_offset,       cudaFuncAttributeMaxDynamicSharedMemorySize, smem1);
    cudaFuncSetAttribute(k_deform,       cudaFuncAttributeMaxDynamicSharedMemorySize, smem2);
    cudaFuncSetAttribute(k_conv_softmax, cudaFuncAttributeMaxDynamicSharedMemorySize, smem3);

    k_offset<<<256, 256, smem1>>>(x, offw, offb, pa);
    k_deform<<<2048, 256, smem2>>>(x, dw, db);
    k_conv_softmax<<<1024, 256, smem3>>>(x, cw, out);
}

// round 2
// speedup vs baseline: 1.0219x; 1.0219x over previous
#include <cuda_runtime.h>

#define BB 8
#define CC 64
#define HH 128
#define WW 128
#define HWSZ (HH*WW)
#define KOFF 18

// scratch (no allocations allowed)
__device__ float g_offset[BB*KOFF*HWSZ];   // post-PReLU offsets [B,18,H,W]
__device__ float g_atten [BB*CC*HWSZ];     // softmax(conv) [B,64,H,W]
__device__ float g_xt    [BB*HWSZ*CC];     // x transposed to NHWC [B,H,W,C]

typedef unsigned long long u64;

__device__ __forceinline__ u64 pk2(float lo, float hi){
    u64 r; asm("mov.b64 %0, {%1,%2};" : "=l"(r) : "f"(lo), "f"(hi)); return r;
}
__device__ __forceinline__ float2 uf2(u64 v){
    float2 f; asm("mov.b64 {%0,%1}, %2;" : "=f"(f.x), "=f"(f.y) : "l"(v)); return f;
}
__device__ __forceinline__ u64 fma2(u64 a, u64 b, u64 c){
    u64 d; asm("fma.rn.f32x2 %0, %1, %2, %3;" : "=l"(d) : "l"(a), "l"(b), "l"(c)); return d;
}

// ---------------------------------------------------------------------------
// T: transpose x NCHW -> NHWC (g_xt). grid 1024 = (b,h), block 256.
// ---------------------------------------------------------------------------
__global__ __launch_bounds__(256) void k_transpose(const float* __restrict__ x)
{
    __shared__ float s[64][129];
    int t = threadIdx.x;
    int b = blockIdx.x >> 7, h = blockIdx.x & 127;
    const float* xb = x + b*CC*HWSZ + h*WW;
    for (int i = t; i < 64*128; i += 256) {
        int c = i >> 7, w = i & 127;
        s[c][w] = xb[c*HWSZ + w];
    }
    __syncthreads();
    float* ob = g_xt + (b*HH + h)*WW*CC;
    for (int i = t; i < 64*128; i += 256) {
        int w = i >> 6, c = i & 63;
        ob[w*CC + c] = s[c][w];
    }
}

// ---------------------------------------------------------------------------
// A: fused conv: 64 logit channels (-> softmax over W -> g_atten)
//    + 18 offset channels (-> PReLU -> g_offset).
// grid 1024 = (b,h); block 512: t<256 logits (32 wq x 8 og, 8 oc x 4 px),
// t>=256 offsets (32 wq x 8 og2, 2-3 oc x 4 px). Shared x tile + cin chunks.
// ---------------------------------------------------------------------------
__global__ __launch_bounds__(512, 1) void k_convA(
    const float* __restrict__ x,  const float* __restrict__ offw,
    const float* __restrict__ offb, const float* __restrict__ pa_,
    const float* __restrict__ cw)
{
    extern __shared__ float sm[];
    float* smx = sm;                              // 64*3*132 floats
    u64*   scw = (u64*)(sm + 64*3*132);           // 64*16*9 dup'd logits weights
    u64*   sow = scw + 64*16*9;                   // 18*16*9 dup'd offset weights

    int t = threadIdx.x;
    int b = blockIdx.x >> 7, h = blockIdx.x & 127;

    // x tile: rows h-1..h+1, padded width 130 (stride 132)
    for (int i = t; i < CC*3*130; i += 512) {
        int c = i / 390; int rem = i - c*390;
        int r = rem / 130; int pc = rem - r*130;
        int iy = h + r - 1, iw = pc - 1;
        float v = 0.f;
        if (iy >= 0 && iy < HH && iw >= 0 && iw < WW)
            v = x[(b*CC + c)*HWSZ + iy*WW + iw];
        smx[(c*3 + r)*132 + pc] = v;
    }

    int wq = t & 31, w0 = wq << 2;
    bool isLog = (t < 256);
    int og = (t >> 5) & 7;
    int cbase = og < 2 ? og*3 : 6 + (og - 2)*2;   // offset-channel base
    int ccnt  = og < 2 ? 3 : 2;                   // offset-channel count

    u64 accL[8][2];
    u64 accO[3][2];
    if (isLog) {
        #pragma unroll
        for (int o = 0; o < 8; o++) { accL[o][0] = 0ULL; accL[o][1] = 0ULL; }
    } else {
        #pragma unroll
        for (int j = 0; j < 3; j++) {
            float bo = (j < ccnt) ? offb[cbase + j] : 0.f;
            accO[j][0] = pk2(bo, bo); accO[j][1] = accO[j][0];
        }
    }

    for (int cch = 0; cch < 4; cch++) {
        __syncthreads();
        for (int i = t; i < CC*16*9; i += 512) {
            int o = i / 144; int rem = i - o*144;
            float v = cw[(o*CC + cch*16)*9 + rem];
            scw[i] = pk2(v, v);
        }
        for (int i = t; i < KOFF*16*9; i += 512) {
            int o = i / 144; int rem = i - o*144;
            float v = offw[(o*CC + cch*16)*9 + rem];
            sow[i] = pk2(v, v);
        }
        __syncthreads();
        #pragma unroll 1
        for (int cl = 0; cl < 16; cl++) {
            int cg = cch*16 + cl;
            #pragma unroll
            for (int ky = 0; ky < 3; ky++) {
                const float* xr = smx + (cg*3 + ky)*132;
                float4 Bv = *(const float4*)(xr + w0);
                float2 Cv = *(const float2*)(xr + w0 + 4);
                u64 P[5];
                P[0] = pk2(Bv.x, Bv.y); P[1] = pk2(Bv.y, Bv.z); P[2] = pk2(Bv.z, Bv.w);
                P[3] = pk2(Bv.w, Cv.x); P[4] = pk2(Cv.x, Cv.y);
                if (isLog) {
                    const u64* wr = scw + (og*8)*144 + cl*9 + ky*3;
                    #pragma unroll
                    for (int kx = 0; kx < 3; kx++) {
                        #pragma unroll
                        for (int o = 0; o < 8; o++) {
                            u64 wv = wr[o*144 + kx];
                            accL[o][0] = fma2(wv, P[kx],     accL[o][0]);
                            accL[o][1] = fma2(wv, P[kx + 2], accL[o][1]);
                        }
                    }
                } else {
                    const u64* wr = sow + cbase*144 + cl*9 + ky*3;
                    #pragma unroll
                    for (int kx = 0; kx < 3; kx++) {
                        #pragma unroll
                        for (int j = 0; j < 3; j++) {
                            if (j < ccnt) {
                                u64 wv = wr[j*144 + kx];
                                accO[j][0] = fma2(wv, P[kx],     accO[j][0]);
                                accO[j][1] = fma2(wv, P[kx + 2], accO[j][1]);
                            }
                        }
                    }
                }
            }
        }
    }

    if (isLog) {
        // softmax over W (warp = full 128-wide row per channel) -> g_atten
        #pragma unroll
        for (int o = 0; o < 8; o++) {
            int oc = og*8 + o;
            float2 u0 = uf2(accL[o][0]), u1 = uf2(accL[o][1]);
            float v0 = u0.x, v1 = u0.y, v2 = u1.x, v3 = u1.y;
            float m = fmaxf(fmaxf(v0, v1), fmaxf(v2, v3));
            #pragma unroll
            for (int s = 16; s > 0; s >>= 1)
                m = fmaxf(m, __shfl_xor_sync(0xffffffffu, m, s));
            float e0 = __expf(v0 - m), e1 = __expf(v1 - m);
            float e2 = __expf(v2 - m), e3 = __expf(v3 - m);
            float smv = e0 + e1 + e2 + e3;
            #pragma unroll
            for (int s = 16; s > 0; s >>= 1)
                smv += __shfl_xor_sync(0xffffffffu, smv, s);
            float inv = 1.0f / smv;
            float4 av = make_float4(e0*inv, e1*inv, e2*inv, e3*inv);
            *(float4*)&g_atten[((b*CC + oc)*HH + h)*WW + w0] = av;
        }
    } else {
        float pa = pa_[0];
        #pragma unroll
        for (int j = 0; j < 3; j++) {
            if (j < ccnt) {
                float2 u0 = uf2(accO[j][0]), u1 = uf2(accO[j][1]);
                float v0 = u0.x, v1 = u0.y, v2 = u1.x, v3 = u1.y;
                v0 = v0 >= 0.f ? v0 : pa*v0;
                v1 = v1 >= 0.f ? v1 : pa*v1;
                v2 = v2 >= 0.f ? v2 : pa*v2;
                v3 = v3 >= 0.f ? v3 : pa*v3;
                float4 ov = make_float4(v0, v1, v2, v3);
                *(float4*)&g_offset[((b*KOFF + cbase + j)*HH + h)*WW + w0] = ov;
            }
        }
    }
}

// ---------------------------------------------------------------------------
// B: deformable grouped conv (NHWC gather) fused with out = atten*feat + x.
// grid 1024 = (b,h), block 256. Per tap: warp-gather (512B loads over both
// x-corners x 64ch + shfl combine) -> smem patch [ci][px] -> smem GEMM.
// ---------------------------------------------------------------------------
__global__ __launch_bounds__(256, 2) void k_deformB(
    const float* __restrict__ x, const float* __restrict__ dw,
    const float* __restrict__ db, float* __restrict__ out)
{
    extern __shared__ float smB[];
    float* soff   = smB;                          // 18*128 floats (9216B)
    u64*   swd    = (u64*)(smB + KOFF*WW);        // 64*8*9 dup'd weights (36864B)
    float* spatch = (float*)(swd + CC*8*9);       // [64ci][132px] (33792B)

    int t = threadIdx.x;
    int b = blockIdx.x >> 7, h = blockIdx.x & 127;

    for (int i = t; i < KOFF*WW; i += 256)
        soff[i] = g_offset[(b*KOFF + (i >> 7))*HWSZ + h*WW + (i & 127)];
    for (int i = t; i < CC*8*9; i += 256) { float v = dw[i]; swd[i] = pk2(v, v); }
    __syncthreads();

    int wq = t & 31, g = t >> 5;       // GEMM mapping
    int wid = t >> 5, l = t & 31;      // gather mapping
    int lh = l & 15, hiL = l >> 4;

    u64 acc[8][2];
    #pragma unroll
    for (int o = 0; o < 8; o++) {
        float bo = db[g*8 + o];
        acc[o][0] = pk2(bo, bo); acc[o][1] = acc[o][0];
    }

    const float* xtb = g_xt + b*HWSZ*CC;

    for (int k = 0; k < 9; k++) {
        int ky = k / 3, kx = k - ky*3;

        // ---- gather phase: warp handles 16 px; per px both corner-rows ----
        #pragma unroll 2
        for (int i2 = 0; i2 < 16; i2++) {
            int px = wid*16 + i2;
            float dy = soff[(2*k)*WW + px];
            float dx = soff[(2*k + 1)*WW + px];
            float ys = (float)(h - 1 + ky) + dy;
            float xs = (float)(px - 1 + kx) + dx;
            float yf = floorf(ys), xf = floorf(xs);
            float ay = ys - yf, ax = xs - xf;
            int iy0 = (int)yf, ix0 = (int)xf;

            int xi = ix0 + hiL;                           // lo half: x0, hi half: x0+1
            float mx = (xi >= 0 && xi < WW) ? 1.f : 0.f;
            int xc = min(max(xi, 0), WW - 1);
            float my0 = (iy0 >= 0  && iy0 < HH)     ? 1.f : 0.f;
            float my1 = (iy0 >= -1 && iy0 + 1 < HH) ? 1.f : 0.f;
            int yc0 = min(max(iy0, 0), HH - 1);
            int yc1 = min(max(iy0 + 1, 0), HH - 1);

            float4 v0 = *(const float4*)(xtb + (yc0*WW + xc)*CC + lh*4);
            float4 v1 = *(const float4*)(xtb + (yc1*WW + xc)*CC + lh*4);

            float axl = hiL ? ax : (1.f - ax);
            float w0l = (1.f - ay)*axl*mx*my0;
            float w1l = ay*axl*mx*my1;

            float s0 = w0l*v0.x + w1l*v1.x;
            float s1 = w0l*v0.y + w1l*v1.y;
            float s2 = w0l*v0.z + w1l*v1.z;
            float s3 = w0l*v0.w + w1l*v1.w;
            s0 += __shfl_xor_sync(0xffffffffu, s0, 16);
            s1 += __shfl_xor_sync(0xffffffffu, s1, 16);
            s2 += __shfl_xor_sync(0xffffffffu, s2, 16);
            s3 += __shfl_xor_sync(0xffffffffu, s3, 16);
            if (hiL == 0) {
                spatch[(lh*4 + 0)*132 + px] = s0;
                spatch[(lh*4 + 1)*132 + px] = s1;
                spatch[(lh*4 + 2)*132 + px] = s2;
                spatch[(lh*4 + 3)*132 + px] = s3;
            }
        }
        __syncthreads();

        // ---- GEMM phase: feat[oc, px] += w[oc,ci,k] * patch[ci,px] ----
        #pragma unroll
        for (int ci = 0; ci < 8; ci++) {
            float4 pv = *(const float4*)(spatch + (g*8 + ci)*132 + wq*4);
            u64 a01 = pk2(pv.x, pv.y), a23 = pk2(pv.z, pv.w);
            const u64* wr = swd + (g*64 + ci)*9 + k;
            #pragma unroll
            for (int o = 0; o < 8; o++) {
                u64 wv = wr[o*72];
                acc[o][0] = fma2(wv, a01, acc[o][0]);
                acc[o][1] = fma2(wv, a23, acc[o][1]);
            }
        }
        __syncthreads();
    }

    // ---- epilogue: out = atten*feat + x ----
    #pragma unroll
    for (int o = 0; o < 8; o++) {
        int oc = g*8 + o;
        float2 flo = uf2(acc[o][0]), fhi = uf2(acc[o][1]);
        int base = ((b*CC + oc)*HH + h)*WW + wq*4;
        float4 at = *(const float4*)(g_atten + base);
        float4 xv = *(const float4*)(x + base);
        float4 ov = make_float4(fmaf(at.x, flo.x, xv.x),
                                fmaf(at.y, flo.y, xv.y),
                                fmaf(at.z, fhi.x, xv.z),
                                fmaf(at.w, fhi.y, xv.w));
        *(float4*)(out + base) = ov;
    }
}

extern "C" void kernel_launch(void* const* d_in, const int* in_sizes, int n_in,
                              void* d_out, int out_size)
{
    const float* x    = (const float*)d_in[0];
    const float* offw = (const float*)d_in[1];
    const float* offb = (const float*)d_in[2];
    const float* pa   = (const float*)d_in[3];
    const float* dw   = (const float*)d_in[4];
    const float* db   = (const float*)d_in[5];
    const float* cw   = (const float*)d_in[6];
    float* out = (float*)d_out;

    const int smemA = 64*3*132*4 + (64*16*9 + 18*16*9)*8;   // 195840
    const int smemB = KOFF*WW*4 + CC*8*9*8 + 64*132*4;      // 79872

    cudaFuncSetAttribute(k_convA,   cudaFuncAttributeMaxDynamicSharedMemorySize, smemA);
    cudaFuncSetAttribute(k_deformB, cudaFuncAttributeMaxDynamicSharedMemorySize, smemB);

    k_transpose<<<1024, 256>>>(x);
    k_convA<<<1024, 512, smemA>>>(x, offw, offb, pa, cw);
    k_deformB<<<1024, 256, smemB>>>(x, dw, db, out);
}